// round 5
// baseline (speedup 1.0000x reference)
#include <cuda_runtime.h>
#include <cuda_bf16.h>
#include <math.h>
#include <stdint.h>
#include <stddef.h>

// ---------------------------------------------------------------------------
#define BATCH 32
#define RES   64
#define CDIM  96
#define NHEAD 3
#define HEADD 32
#define LTOT  (RES*RES)          // 4096
#define MTOT  (BATCH*LTOT)       // 131072
#define NWIN  (BATCH*64)         // 2048
#define HID   384
#define SCALEF 0.17677669529663687f
#define SPAD  104                // bf16 smem row stride (conflict-free ldmatrix)

typedef __nv_bfloat16 bf16;
typedef __nv_bfloat162 bf162;

// Scratch
__device__ __align__(256) bf16  g_qkv [(size_t)MTOT*3*CDIM];
__device__ __align__(256) bf16  g_o   [(size_t)MTOT*CDIM];
__device__ __align__(256) float g_x1  [(size_t)MTOT*CDIM];
__device__ __align__(256) bf16  g_h2  [(size_t)MTOT*CDIM];
__device__ __align__(256) bf16  g_hid [(size_t)MTOT*HID];
__device__ __align__(256) float g_scr [(size_t)NWIN*NHEAD*64*64];
__device__ __align__(256) bf16  g_wqkvT[3*CDIM*CDIM];
__device__ __align__(256) bf16  g_wprojT[CDIM*CDIM];
__device__ __align__(256) bf16  g_wfc1T[HID*CDIM];
__device__ __align__(256) bf16  g_wfc2T[CDIM*HID];

// ---------------------------------------------------------------------------
__device__ __forceinline__ uint32_t smem_u32(const void* p) {
    uint32_t a;
    asm("{ .reg .u64 t; cvta.to.shared.u64 t, %1; cvt.u32.u64 %0, t; }" : "=r"(a) : "l"(p));
    return a;
}
#define CP_ASYNC16(dst, src) \
    asm volatile("cp.async.cg.shared.global [%0], [%1], 16;" :: "r"(dst), "l"(src))
#define CP_COMMIT()  asm volatile("cp.async.commit_group;" ::: "memory")
#define CP_WAIT_ALL() asm volatile("cp.async.wait_all;" ::: "memory")
#define CP_WAIT1()   asm volatile("cp.async.wait_group 1;" ::: "memory")

__device__ __forceinline__ void ldm_x4(uint32_t* r, uint32_t addr) {
    asm volatile("ldmatrix.sync.aligned.m8n8.x4.shared.b16 {%0,%1,%2,%3}, [%4];"
        : "=r"(r[0]), "=r"(r[1]), "=r"(r[2]), "=r"(r[3]) : "r"(addr));
}
__device__ __forceinline__ void mma16816(float* d, const uint32_t* a, const uint32_t* b) {
    asm volatile("mma.sync.aligned.m16n8k16.row.col.f32.bf16.bf16.f32 "
        "{%0,%1,%2,%3}, {%4,%5,%6,%7}, {%8,%9}, {%0,%1,%2,%3};"
        : "+f"(d[0]), "+f"(d[1]), "+f"(d[2]), "+f"(d[3])
        : "r"(a[0]), "r"(a[1]), "r"(a[2]), "r"(a[3]), "r"(b[0]), "r"(b[1]));
}

// window-ordered row m -> token linear offset (b*LTOT + l)
__device__ __forceinline__ size_t win2tok(int m) {
    int win = m >> 6, t = m & 63;
    int bb = win >> 6, wi = win & 63;
    int wh = wi >> 3, ww = wi & 7;
    int gh = t >> 3,  gw = t & 7;
    int l = ((wh * 8 + gh) << 6) + ww * 8 + gw;
    return (size_t)bb * LTOT + l;
}

// ---------------------------------------------------------------------------
// One fused weight transpose kernel: out[n*K+k] = (bf16)W[k*N+n]
// ---------------------------------------------------------------------------
__global__ void wt_all_kernel(const float* __restrict__ wq, const float* __restrict__ wp,
                              const float* __restrict__ w1, const float* __restrict__ w2,
                              bf16* __restrict__ oq, bf16* __restrict__ op,
                              bf16* __restrict__ o1, bf16* __restrict__ o2)
{
    int i = blockIdx.x * 256 + threadIdx.x;
    const int S0 = 3*CDIM*CDIM;          // 27648
    const int S1 = S0 + CDIM*CDIM;       // 36864
    const int S2 = S1 + HID*CDIM;        // 73728
    const int S3 = S2 + CDIM*HID;        // 110592
    if (i < S0) {
        int n = i / CDIM, k = i - n * CDIM;
        oq[i] = __float2bfloat16(wq[(size_t)k * (3*CDIM) + n]);
    } else if (i < S1) {
        int j = i - S0; int n = j / CDIM, k = j - n * CDIM;
        op[j] = __float2bfloat16(wp[(size_t)k * CDIM + n]);
    } else if (i < S2) {
        int j = i - S1; int n = j / CDIM, k = j - n * CDIM;
        o1[j] = __float2bfloat16(w1[(size_t)k * HID + n]);
    } else if (i < S3) {
        int j = i - S2; int n = j / HID, k = j - n * HID;
        o2[j] = __float2bfloat16(w2[(size_t)k * CDIM + n]);
    }
}

// ---------------------------------------------------------------------------
// Kernel 1: fused LN1 (+window remap) -> smem A, B(all 288 rows) resident,
// 3 N-tiles -> qkv bf16.   grid.x = MTOT/128, 256 threads.
// smem: As 128xSPAD bf16 @0 (26624B), Bs 288xSPAD bf16 @26624 (59904B)
// ---------------------------------------------------------------------------
__global__ __launch_bounds__(256) void qkv_kernel(
    const float* __restrict__ x, const float* __restrict__ g1,
    const float* __restrict__ bt1, const bf16* __restrict__ Bt,
    const float* __restrict__ bias, bf16* __restrict__ outp)
{
    extern __shared__ char sm[];
    bf16* As = (bf16*)sm;
    uint32_t a_base = smem_u32(sm);
    uint32_t b_base = a_base + 26624;

    int tid = threadIdx.x, lane = tid & 31, wid = tid >> 5;
    int warp_m = wid & 3, warp_n = wid >> 2;
    int m0 = blockIdx.x * 128;

    // B: 288 rows x 12 chunks = 3456 cp.async
    #pragma unroll
    for (int i = 0; i < 14; i++) {
        int idx = tid + i * 256;
        if (idx < 3456) {
            int r = idx / 12, c = idx % 12;
            CP_ASYNC16(b_base + (r * SPAD + c * 8) * 2, Bt + (size_t)r * CDIM + c * 8);
        }
    }
    CP_COMMIT();

    // LN1: warp handles 16 rows
    #pragma unroll
    for (int i = 0; i < 16; i++) {
        int r = wid * 16 + i;
        const float* xr = x + win2tok(m0 + r) * CDIM;
        float v0 = xr[lane], v1 = xr[lane+32], v2 = xr[lane+64];
        float s = v0 + v1 + v2;
        #pragma unroll
        for (int o = 16; o; o >>= 1) s += __shfl_xor_sync(0xffffffffu, s, o);
        float mean = s * (1.0f/96.0f);
        float d0 = v0-mean, d1 = v1-mean, d2 = v2-mean;
        float ss = d0*d0 + d1*d1 + d2*d2;
        #pragma unroll
        for (int o = 16; o; o >>= 1) ss += __shfl_xor_sync(0xffffffffu, ss, o);
        float inv = rsqrtf(ss * (1.0f/96.0f) + 1e-5f);
        As[r * SPAD + lane]      = __float2bfloat16(d0 * inv * g1[lane]    + bt1[lane]);
        As[r * SPAD + lane + 32] = __float2bfloat16(d1 * inv * g1[lane+32] + bt1[lane+32]);
        As[r * SPAD + lane + 64] = __float2bfloat16(d2 * inv * g1[lane+64] + bt1[lane+64]);
    }
    CP_WAIT_ALL();
    __syncthreads();

    int lrow = lane & 15, lcol8 = (lane >> 4) * 8;
    int lr = lane >> 2, lc = (lane & 3) * 2;

    #pragma unroll
    for (int nt = 0; nt < 3; nt++) {
        float acc[2][6][4] = {};
        #pragma unroll
        for (int ks = 0; ks < 6; ks++) {
            uint32_t a_frag[2][4], b_frag[6][2];
            #pragma unroll
            for (int mf = 0; mf < 2; mf++)
                ldm_x4(a_frag[mf], a_base + ((warp_m*32 + mf*16 + lrow) * SPAD + ks*16 + lcol8) * 2);
            #pragma unroll
            for (int nf2 = 0; nf2 < 3; nf2++) {
                uint32_t r4[4];
                ldm_x4(r4, b_base + ((nt*96 + warp_n*48 + nf2*16 + lrow) * SPAD + ks*16 + lcol8) * 2);
                b_frag[nf2*2  ][0] = r4[0]; b_frag[nf2*2  ][1] = r4[2];
                b_frag[nf2*2+1][0] = r4[1]; b_frag[nf2*2+1][1] = r4[3];
            }
            #pragma unroll
            for (int mf = 0; mf < 2; mf++)
                #pragma unroll
                for (int nf = 0; nf < 6; nf++)
                    mma16816(acc[mf][nf], a_frag[mf], b_frag[nf]);
        }
        // epilogue -> bf16 qkv
        #pragma unroll
        for (int mf = 0; mf < 2; mf++)
            #pragma unroll
            for (int half = 0; half < 2; half++) {
                int m = m0 + warp_m*32 + mf*16 + lr + half*8;
                size_t rowoff = (size_t)m * (3*CDIM);
                #pragma unroll
                for (int nf = 0; nf < 6; nf++) {
                    int col = nt*96 + warp_n*48 + nf*8 + lc;
                    float c0 = acc[mf][nf][half*2+0] + __ldg(bias + col);
                    float c1 = acc[mf][nf][half*2+1] + __ldg(bias + col + 1);
                    *(bf162*)(outp + rowoff + col) = __float22bfloat162_rn(make_float2(c0, c1));
                }
            }
    }
}

// ---------------------------------------------------------------------------
// Kernel 3: proj GEMM + residual + fused LN2.
// Writes x1 (fp32, token order) and h2 (bf16, token order).
// smem: As @0 (26624), Bs @26624 (19968), x1s fp32 128x100 @46592 (51200)
// ---------------------------------------------------------------------------
__global__ __launch_bounds__(256) void proj_kernel(
    const bf16* __restrict__ A, const bf16* __restrict__ Bt,
    const float* __restrict__ bias, const float* __restrict__ xres,
    const float* __restrict__ g2, const float* __restrict__ bt2,
    float* __restrict__ x1, bf16* __restrict__ h2)
{
    extern __shared__ char sm[];
    uint32_t a_base = smem_u32(sm);
    uint32_t b_base = a_base + 26624;
    float* x1s = (float*)(sm + 46592);   // stride 100

    int tid = threadIdx.x, lane = tid & 31, wid = tid >> 5;
    int warp_m = wid & 3, warp_n = wid >> 2;
    int m0 = blockIdx.x * 128;

    // A: 128 x 12 chunks
    #pragma unroll
    for (int i = 0; i < 6; i++) {
        int idx = tid + i * 256;
        int r = idx / 12, c = idx % 12;
        CP_ASYNC16(a_base + (r * SPAD + c * 8) * 2, A + (size_t)(m0 + r) * CDIM + c * 8);
    }
    // B: 96 x 12
    #pragma unroll
    for (int i = 0; i < 5; i++) {
        int idx = tid + i * 256;
        if (idx < 1152) {
            int r = idx / 12, c = idx % 12;
            CP_ASYNC16(b_base + (r * SPAD + c * 8) * 2, Bt + (size_t)r * CDIM + c * 8);
        }
    }
    CP_WAIT_ALL();
    __syncthreads();

    int lrow = lane & 15, lcol8 = (lane >> 4) * 8;
    int lr = lane >> 2, lc = (lane & 3) * 2;

    float acc[2][6][4] = {};
    #pragma unroll
    for (int ks = 0; ks < 6; ks++) {
        uint32_t a_frag[2][4], b_frag[6][2];
        #pragma unroll
        for (int mf = 0; mf < 2; mf++)
            ldm_x4(a_frag[mf], a_base + ((warp_m*32 + mf*16 + lrow) * SPAD + ks*16 + lcol8) * 2);
        #pragma unroll
        for (int nf2 = 0; nf2 < 3; nf2++) {
            uint32_t r4[4];
            ldm_x4(r4, b_base + ((warp_n*48 + nf2*16 + lrow) * SPAD + ks*16 + lcol8) * 2);
            b_frag[nf2*2  ][0] = r4[0]; b_frag[nf2*2  ][1] = r4[2];
            b_frag[nf2*2+1][0] = r4[1]; b_frag[nf2*2+1][1] = r4[3];
        }
        #pragma unroll
        for (int mf = 0; mf < 2; mf++)
            #pragma unroll
            for (int nf = 0; nf < 6; nf++)
                mma16816(acc[mf][nf], a_frag[mf], b_frag[nf]);
    }
    __syncthreads();   // As/Bs dead; x1s region is separate anyway

    // epilogue: x1 = acc + bias + x(token) ; store gmem + smem
    #pragma unroll
    for (int mf = 0; mf < 2; mf++)
        #pragma unroll
        for (int half = 0; half < 2; half++) {
            int rloc = warp_m*32 + mf*16 + lr + half*8;
            size_t rowoff = win2tok(m0 + rloc) * CDIM;
            #pragma unroll
            for (int nf = 0; nf < 6; nf++) {
                int col = warp_n*48 + nf*8 + lc;
                float2 rv = *(const float2*)(xres + rowoff + col);
                float c0 = acc[mf][nf][half*2+0] + __ldg(bias + col)     + rv.x;
                float c1 = acc[mf][nf][half*2+1] + __ldg(bias + col + 1) + rv.y;
                *(float2*)(x1 + rowoff + col) = make_float2(c0, c1);
                x1s[rloc * 100 + col] = c0;
                x1s[rloc * 100 + col + 1] = c1;
            }
        }
    __syncthreads();

    // LN2 per row -> h2 bf16 (token order)
    #pragma unroll
    for (int i = 0; i < 16; i++) {
        int r = wid * 16 + i;
        float v0 = x1s[r*100 + lane], v1 = x1s[r*100 + lane+32], v2 = x1s[r*100 + lane+64];
        float s = v0 + v1 + v2;
        #pragma unroll
        for (int o = 16; o; o >>= 1) s += __shfl_xor_sync(0xffffffffu, s, o);
        float mean = s * (1.0f/96.0f);
        float d0 = v0-mean, d1 = v1-mean, d2 = v2-mean;
        float ss = d0*d0 + d1*d1 + d2*d2;
        #pragma unroll
        for (int o = 16; o; o >>= 1) ss += __shfl_xor_sync(0xffffffffu, ss, o);
        float inv = rsqrtf(ss * (1.0f/96.0f) + 1e-5f);
        bf16* orow = h2 + win2tok(m0 + r) * CDIM;
        orow[lane]    = __float2bfloat16(d0 * inv * g2[lane]    + bt2[lane]);
        orow[lane+32] = __float2bfloat16(d1 * inv * g2[lane+32] + bt2[lane+32]);
        orow[lane+64] = __float2bfloat16(d2 * inv * g2[lane+64] + bt2[lane+64]);
    }
}

// ---------------------------------------------------------------------------
// Kernel 4: fc1 + exact GELU. B all 384 rows resident; 4 N-tiles.
// smem: As @0 (26624), Bs 384xSPAD @26624 (79872) -> 106496 total
// ---------------------------------------------------------------------------
__global__ __launch_bounds__(256) void fc1_kernel(
    const bf16* __restrict__ A, const bf16* __restrict__ Bt,
    const float* __restrict__ bias, bf16* __restrict__ outp)
{
    extern __shared__ char sm[];
    uint32_t a_base = smem_u32(sm);
    uint32_t b_base = a_base + 26624;

    int tid = threadIdx.x, lane = tid & 31, wid = tid >> 5;
    int warp_m = wid & 3, warp_n = wid >> 2;
    int m0 = blockIdx.x * 128;

    #pragma unroll
    for (int i = 0; i < 6; i++) {
        int idx = tid + i * 256;
        int r = idx / 12, c = idx % 12;
        CP_ASYNC16(a_base + (r * SPAD + c * 8) * 2, A + (size_t)(m0 + r) * CDIM + c * 8);
    }
    #pragma unroll
    for (int i = 0; i < 18; i++) {
        int idx = tid + i * 256;
        if (idx < 4608) {
            int r = idx / 12, c = idx % 12;
            CP_ASYNC16(b_base + (r * SPAD + c * 8) * 2, Bt + (size_t)r * CDIM + c * 8);
        }
    }
    CP_WAIT_ALL();
    __syncthreads();

    int lrow = lane & 15, lcol8 = (lane >> 4) * 8;
    int lr = lane >> 2, lc = (lane & 3) * 2;

    #pragma unroll
    for (int nt = 0; nt < 4; nt++) {
        float acc[2][6][4] = {};
        #pragma unroll
        for (int ks = 0; ks < 6; ks++) {
            uint32_t a_frag[2][4], b_frag[6][2];
            #pragma unroll
            for (int mf = 0; mf < 2; mf++)
                ldm_x4(a_frag[mf], a_base + ((warp_m*32 + mf*16 + lrow) * SPAD + ks*16 + lcol8) * 2);
            #pragma unroll
            for (int nf2 = 0; nf2 < 3; nf2++) {
                uint32_t r4[4];
                ldm_x4(r4, b_base + ((nt*96 + warp_n*48 + nf2*16 + lrow) * SPAD + ks*16 + lcol8) * 2);
                b_frag[nf2*2  ][0] = r4[0]; b_frag[nf2*2  ][1] = r4[2];
                b_frag[nf2*2+1][0] = r4[1]; b_frag[nf2*2+1][1] = r4[3];
            }
            #pragma unroll
            for (int mf = 0; mf < 2; mf++)
                #pragma unroll
                for (int nf = 0; nf < 6; nf++)
                    mma16816(acc[mf][nf], a_frag[mf], b_frag[nf]);
        }
        #pragma unroll
        for (int mf = 0; mf < 2; mf++)
            #pragma unroll
            for (int half = 0; half < 2; half++) {
                int m = m0 + warp_m*32 + mf*16 + lr + half*8;
                size_t rowoff = (size_t)m * HID;
                #pragma unroll
                for (int nf = 0; nf < 6; nf++) {
                    int col = nt*96 + warp_n*48 + nf*8 + lc;
                    float c0 = acc[mf][nf][half*2+0] + __ldg(bias + col);
                    float c1 = acc[mf][nf][half*2+1] + __ldg(bias + col + 1);
                    c0 = c0 * normcdff(c0); c1 = c1 * normcdff(c1);
                    *(bf162*)(outp + rowoff + col) = __float22bfloat162_rn(make_float2(c0, c1));
                }
            }
    }
}

// ---------------------------------------------------------------------------
// Kernel 5: fc2 (K=384, 4 chunks double-buffered) + residual -> y fp32.
// smem: As[2] @0,@26624 ; Bs[2] @53248,@73216 -> 93184 total
// ---------------------------------------------------------------------------
__global__ __launch_bounds__(256) void fc2_kernel(
    const bf16* __restrict__ A, const bf16* __restrict__ Bt,
    const float* __restrict__ bias, const float* __restrict__ res,
    float* __restrict__ outp)
{
    extern __shared__ char sm[];
    uint32_t sbase = smem_u32(sm);

    int tid = threadIdx.x, lane = tid & 31, wid = tid >> 5;
    int warp_m = wid & 3, warp_n = wid >> 2;
    int m0 = blockIdx.x * 128;

    auto prefetch = [&](int kc, int buf) {
        uint32_t a_b = sbase + buf * 26624;
        uint32_t b_b = sbase + 53248 + buf * 19968;
        #pragma unroll
        for (int i = 0; i < 6; i++) {
            int idx = tid + i * 256;
            int r = idx / 12, c = idx % 12;
            CP_ASYNC16(a_b + (r * SPAD + c * 8) * 2,
                       A + (size_t)(m0 + r) * HID + kc * 96 + c * 8);
        }
        #pragma unroll
        for (int i = 0; i < 5; i++) {
            int idx = tid + i * 256;
            if (idx < 1152) {
                int r = idx / 12, c = idx % 12;
                CP_ASYNC16(b_b + (r * SPAD + c * 8) * 2,
                           Bt + (size_t)r * HID + kc * 96 + c * 8);
            }
        }
    };

    float acc[2][6][4] = {};
    int lrow = lane & 15, lcol8 = (lane >> 4) * 8;
    int lr = lane >> 2, lc = (lane & 3) * 2;

    prefetch(0, 0); CP_COMMIT();
    #pragma unroll
    for (int kc = 0; kc < 4; kc++) {
        if (kc < 3) { prefetch(kc + 1, (kc + 1) & 1); CP_COMMIT(); CP_WAIT1(); }
        else        { CP_WAIT_ALL(); }
        __syncthreads();
        uint32_t a_b = sbase + (kc & 1) * 26624;
        uint32_t b_b = sbase + 53248 + (kc & 1) * 19968;
        #pragma unroll
        for (int ks = 0; ks < 6; ks++) {
            uint32_t a_frag[2][4], b_frag[6][2];
            #pragma unroll
            for (int mf = 0; mf < 2; mf++)
                ldm_x4(a_frag[mf], a_b + ((warp_m*32 + mf*16 + lrow) * SPAD + ks*16 + lcol8) * 2);
            #pragma unroll
            for (int nf2 = 0; nf2 < 3; nf2++) {
                uint32_t r4[4];
                ldm_x4(r4, b_b + ((warp_n*48 + nf2*16 + lrow) * SPAD + ks*16 + lcol8) * 2);
                b_frag[nf2*2  ][0] = r4[0]; b_frag[nf2*2  ][1] = r4[2];
                b_frag[nf2*2+1][0] = r4[1]; b_frag[nf2*2+1][1] = r4[3];
            }
            #pragma unroll
            for (int mf = 0; mf < 2; mf++)
                #pragma unroll
                for (int nf = 0; nf < 6; nf++)
                    mma16816(acc[mf][nf], a_frag[mf], b_frag[nf]);
        }
        if (kc < 3) __syncthreads();
    }

    #pragma unroll
    for (int mf = 0; mf < 2; mf++)
        #pragma unroll
        for (int half = 0; half < 2; half++) {
            int m = m0 + warp_m*32 + mf*16 + lr + half*8;
            size_t rowoff = (size_t)m * CDIM;
            #pragma unroll
            for (int nf = 0; nf < 6; nf++) {
                int col = warp_n*48 + nf*8 + lc;
                float2 rv = *(const float2*)(res + rowoff + col);
                float c0 = acc[mf][nf][half*2+0] + __ldg(bias + col)     + rv.x;
                float c1 = acc[mf][nf][half*2+1] + __ldg(bias + col + 1) + rv.y;
                *(float2*)(outp + rowoff + col) = make_float2(c0, c1);
            }
        }
}

// ---------------------------------------------------------------------------
// Kernel 2: windowed attention + LePE
// ---------------------------------------------------------------------------
__global__ __launch_bounds__(64) void attn_kernel(
    const bf16* __restrict__ qkv, const float* __restrict__ wle,
    const float* __restrict__ ble, float* __restrict__ attn_out,
    bf16* __restrict__ ob)
{
    const int win  = blockIdx.x / NHEAD;
    const int head = blockIdx.x % NHEAD;
    const int t    = threadIdx.x;

    __shared__ float ks[64][36];
    __shared__ float vs[64][36];

    const bf16* base = qkv + (size_t)(win * 64 + t) * (3 * CDIM) + head * HEADD;
    float q[32];
    #pragma unroll
    for (int i = 0; i < 4; i++) {
        uint4 rq = *(const uint4*)(base + i * 8);
        uint4 rk = *(const uint4*)(base + CDIM + i * 8);
        uint4 rv = *(const uint4*)(base + 2 * CDIM + i * 8);
        const bf162* pq = (const bf162*)&rq;
        const bf162* pk = (const bf162*)&rk;
        const bf162* pv = (const bf162*)&rv;
        #pragma unroll
        for (int j = 0; j < 4; j++) {
            float2 fq = __bfloat1622float2(pq[j]);
            float2 fk = __bfloat1622float2(pk[j]);
            float2 fv = __bfloat1622float2(pv[j]);
            q[i*8 + 2*j] = fq.x; q[i*8 + 2*j + 1] = fq.y;
            ks[t][i*8 + 2*j] = fk.x; ks[t][i*8 + 2*j + 1] = fk.y;
            vs[t][i*8 + 2*j] = fv.x; vs[t][i*8 + 2*j + 1] = fv.y;
        }
    }
    __syncthreads();

    float p[64];
    #pragma unroll
    for (int j0 = 0; j0 < 64; j0 += 4) {
        float a0 = 0.f, a1 = 0.f, a2 = 0.f, a3 = 0.f;
        #pragma unroll
        for (int d4 = 0; d4 < 8; d4++) {
            float4 k0 = *(const float4*)&ks[j0+0][d4*4];
            float4 k1 = *(const float4*)&ks[j0+1][d4*4];
            float4 k2 = *(const float4*)&ks[j0+2][d4*4];
            float4 k3 = *(const float4*)&ks[j0+3][d4*4];
            float q0 = q[d4*4], q1 = q[d4*4+1], q2 = q[d4*4+2], q3 = q[d4*4+3];
            a0 += q0*k0.x + q1*k0.y + q2*k0.z + q3*k0.w;
            a1 += q0*k1.x + q1*k1.y + q2*k1.z + q3*k1.w;
            a2 += q0*k2.x + q1*k2.y + q2*k2.z + q3*k2.w;
            a3 += q0*k3.x + q1*k3.y + q2*k3.z + q3*k3.w;
        }
        p[j0] = a0 * SCALEF; p[j0+1] = a1 * SCALEF;
        p[j0+2] = a2 * SCALEF; p[j0+3] = a3 * SCALEF;
    }

    float mx = -1e30f;
    #pragma unroll
    for (int j = 0; j < 64; j++) mx = fmaxf(mx, p[j]);
    float sum = 0.f;
    #pragma unroll
    for (int j = 0; j < 64; j++) { p[j] = __expf(p[j] - mx); sum += p[j]; }
    float invs = 1.0f / sum;
    #pragma unroll
    for (int j = 0; j < 64; j++) p[j] *= invs;

    float* ar = attn_out + ((size_t)(win * NHEAD + head) * 64 + t) * 64;
    #pragma unroll
    for (int j4 = 0; j4 < 16; j4++) {
        float4 w; w.x = p[j4*4]; w.y = p[j4*4+1]; w.z = p[j4*4+2]; w.w = p[j4*4+3];
        *(float4*)(ar + j4 * 4) = w;
    }

    float acc[32] = {};
    #pragma unroll
    for (int j = 0; j < 64; j++) {
        float pj = p[j];
        #pragma unroll
        for (int d4 = 0; d4 < 8; d4++) {
            float4 vv = *(const float4*)&vs[j][d4*4];
            acc[d4*4+0] += pj * vv.x; acc[d4*4+1] += pj * vv.y;
            acc[d4*4+2] += pj * vv.z; acc[d4*4+3] += pj * vv.w;
        }
    }

    int gh = t >> 3, gw = t & 7;
    #pragma unroll
    for (int d = 0; d < 32; d++) {
        int c = head * HEADD + d;
        float le = 0.f;
        #pragma unroll
        for (int dh = -1; dh <= 1; dh++) {
            int ih = gh + dh;
            if (ih < 0 || ih > 7) continue;
            #pragma unroll
            for (int dw = -1; dw <= 1; dw++) {
                int iw = gw + dw;
                if (iw < 0 || iw > 7) continue;
                le += vs[ih * 8 + iw][d] * __ldg(wle + (size_t)c * 9 + (dh+1)*3 + (dw+1));
            }
        }
        acc[d] += le + __ldg(ble + c);
    }

    bf162 hh[16];
    #pragma unroll
    for (int j = 0; j < 16; j++)
        hh[j] = __float22bfloat162_rn(make_float2(acc[2*j], acc[2*j+1]));
    uint4* orow = (uint4*)(ob + (size_t)(win * 64 + t) * CDIM + head * HEADD);
    const uint4* src = (const uint4*)hh;
    orow[0] = src[0]; orow[1] = src[1]; orow[2] = src[2]; orow[3] = src[3];
}

// ---------------------------------------------------------------------------
extern "C" void kernel_launch(void* const* d_in, const int* in_sizes, int n_in,
                              void* d_out, int out_size)
{
    const float* x      = (const float*)d_in[0];
    const float* w_qkv  = (const float*)d_in[1];
    const float* b_qkv  = (const float*)d_in[2];
    const float* w_lepe = (const float*)d_in[3];
    const float* b_lepe = (const float*)d_in[4];
    const float* w_proj = (const float*)d_in[5];
    const float* b_proj = (const float*)d_in[6];
    const float* g1     = (const float*)d_in[7];
    const float* bt1    = (const float*)d_in[8];
    const float* g2     = (const float*)d_in[9];
    const float* bt2    = (const float*)d_in[10];
    const float* w_fc1  = (const float*)d_in[11];
    const float* b_fc1  = (const float*)d_in[12];
    const float* w_fc2  = (const float*)d_in[13];
    const float* b_fc2  = (const float*)d_in[14];

    bf16 *qkv, *ob, *h2, *hid, *wq, *wp, *w1, *w2;
    float *x1, *scr;
    cudaGetSymbolAddress((void**)&qkv, g_qkv);
    cudaGetSymbolAddress((void**)&ob,  g_o);
    cudaGetSymbolAddress((void**)&x1,  g_x1);
    cudaGetSymbolAddress((void**)&h2,  g_h2);
    cudaGetSymbolAddress((void**)&hid, g_hid);
    cudaGetSymbolAddress((void**)&scr, g_scr);
    cudaGetSymbolAddress((void**)&wq,  g_wqkvT);
    cudaGetSymbolAddress((void**)&wp,  g_wprojT);
    cudaGetSymbolAddress((void**)&w1,  g_wfc1T);
    cudaGetSymbolAddress((void**)&w2,  g_wfc2T);

    static bool attr_done = false;
    if (!attr_done) {
        cudaFuncSetAttribute(qkv_kernel,  cudaFuncAttributeMaxDynamicSharedMemorySize, 86528);
        cudaFuncSetAttribute(proj_kernel, cudaFuncAttributeMaxDynamicSharedMemorySize, 97792);
        cudaFuncSetAttribute(fc1_kernel,  cudaFuncAttributeMaxDynamicSharedMemorySize, 106496);
        cudaFuncSetAttribute(fc2_kernel,  cudaFuncAttributeMaxDynamicSharedMemorySize, 93184);
        attr_done = true;
    }

    const long YE = (long)MTOT * CDIM;
    const long AE = (long)NWIN * NHEAD * 64 * 64;
    float* out = (float*)d_out;
    float* y_out = out;
    float* a_out;
    if ((long)out_size >= YE + AE)      { a_out = out + YE; }
    else if ((long)out_size == AE)      { y_out = scr; a_out = out; }
    else                                { a_out = scr; }

    wt_all_kernel<<<432, 256>>>(w_qkv, w_proj, w_fc1, w_fc2, wq, wp, w1, w2);
    qkv_kernel<<<MTOT/128, 256, 86528>>>(x, g1, bt1, wq, b_qkv, qkv);
    attn_kernel<<<NWIN*NHEAD, 64>>>(qkv, w_lepe, b_lepe, a_out, ob);
    proj_kernel<<<MTOT/128, 256, 97792>>>(ob, wp, b_proj, x, g2, bt2, x1, h2);
    fc1_kernel<<<MTOT/128, 256, 106496>>>(h2, w1, b_fc1, hid);
    fc2_kernel<<<MTOT/128, 256, 93184>>>(hid, w2, b_fc2, x1, y_out);
}